// round 10
// baseline (speedup 1.0000x reference)
#include <cuda_runtime.h>
#include <cuda_fp16.h>
#include <math.h>

#define NE 3200000
#define NN 100000
#define EPT 4
#define SCAN_T 512
#define SCAN_NB 196   // 196*512 = 100352 >= NN

// ---------------- device state ----------------
__device__ float g_W1[16*5];
__device__ float g_b1[16];
__device__ float g_W2[32*16];
__device__ float g_b2[32];
__device__ float g_W3[16*35];
__device__ float g_b3[16];
__device__ float g_W4[16];
__device__ float g_b4[1];

__device__ int4   g_sedge[NE];      // dst-sorted {src, dst, ea.x bits, ea.y bits}
__device__ int    g_cnt[NN];
__device__ int    g_off[NN];
__device__ int    g_pos[NN];
__device__ int    g_bsum[SCAN_NB];
__device__ int    g_bpre[SCAN_NB];

__device__ float4   g_xp[NN];       // (x0, x1, x2, unused)
__device__ unsigned g_agg[NN * 32]; // fp32 bit patterns, all values >= 0
__device__ int      g_is_i32;

__device__ __forceinline__ float softplusf(float v) {
    return (v > 20.f) ? v : log1pf(expf(v));
}

__device__ __forceinline__ unsigned hmax2_bits(unsigned a, unsigned b) {
    __half2 ha = *reinterpret_cast<__half2*>(&a);
    __half2 hb = *reinterpret_cast<__half2*>(&b);
    __half2 r = __hmax2(ha, hb);
    return *reinterpret_cast<unsigned*>(&r);
}

// ---------------- fused prep: reset flag, zero cnt+agg, pack x ----------------
__global__ void prep_init(const float* __restrict__ x)
{
    int i = blockIdx.x * blockDim.x + threadIdx.x;
    if (i == 0) g_is_i32 = 0;
    if (i < NN) {
        g_cnt[i] = 0;
        g_xp[i] = make_float4(x[3*i + 0], x[3*i + 1], x[3*i + 2], 0.f);
    }
    if (i < (NN * 32) / 4)
        reinterpret_cast<uint4*>(g_agg)[i] = make_uint4(0u, 0u, 0u, 0u);
}

__global__ void detect_layout(const unsigned* __restrict__ ei_words)
{
    int t = blockIdx.x * blockDim.x + threadIdx.x;   // 512 samples
    if (ei_words[2*t + 1] != 0u) atomicExch(&g_is_i32, 1);
}

// ---------------- prep: sample Bayesian weights ----------------
__global__ void prep_weights(
    const float* w1m, const float* w1r, const float* b1m, const float* b1r, const float* e1w, const float* e1b,
    const float* w2m, const float* w2r, const float* b2m, const float* b2r, const float* e2w, const float* e2b,
    const float* w3m, const float* w3r, const float* b3m, const float* b3r, const float* e3w, const float* e3b,
    const float* w4m, const float* w4r, const float* b4m, const float* b4r, const float* e4w, const float* e4b)
{
    int t = blockIdx.x * blockDim.x + threadIdx.x;
    int stride = gridDim.x * blockDim.x;
    for (int i = t; i < 16*5;  i += stride) g_W1[i] = w1m[i] + softplusf(w1r[i]) * e1w[i];
    for (int i = t; i < 16;    i += stride) g_b1[i] = b1m[i] + softplusf(b1r[i]) * e1b[i];
    for (int i = t; i < 32*16; i += stride) g_W2[i] = w2m[i] + softplusf(w2r[i]) * e2w[i];
    for (int i = t; i < 32;    i += stride) g_b2[i] = b2m[i] + softplusf(b2r[i]) * e2b[i];
    for (int i = t; i < 16*35; i += stride) g_W3[i] = w3m[i] + softplusf(w3r[i]) * e3w[i];
    for (int i = t; i < 16;    i += stride) g_b3[i] = b3m[i] + softplusf(b3r[i]) * e3b[i];
    for (int i = t; i < 16;    i += stride) g_W4[i] = w4m[i] + softplusf(w4r[i]) * e4w[i];
    for (int i = t; i < 1;     i += stride) g_b4[i] = b4m[i] + softplusf(b4r[i]) * e4b[i];
}

// ---------------- helpers to read edge index in either width ----------------
__device__ __forceinline__ int load_src(const int* ei, int e) {
    int s = g_is_i32 ? ei[e] : ei[2*e];
    return ((unsigned)s >= NN) ? 0 : s;
}
__device__ __forceinline__ int load_dst(const int* ei, int e) {
    int d = g_is_i32 ? ei[NE + e] : ei[2*(NE + e)];
    return ((unsigned)d >= NN) ? 0 : d;
}

// ---------------- histogram ----------------
__global__ void hist_kernel(const int* __restrict__ ei)
{
    int e = blockIdx.x * blockDim.x + threadIdx.x;
    if (e < NE) atomicAdd(&g_cnt[load_dst(ei, e)], 1);
}

// ---------------- scan ----------------
__global__ void scan_blocks()
{
    __shared__ int s[SCAN_T];
    int t = threadIdx.x;
    int i = blockIdx.x * SCAN_T + t;
    int v = (i < NN) ? g_cnt[i] : 0;
    s[t] = v;
    __syncthreads();
    for (int off = 1; off < SCAN_T; off <<= 1) {
        int x = (t >= off) ? s[t - off] : 0;
        __syncthreads();
        s[t] += x;
        __syncthreads();
    }
    if (i < NN) g_off[i] = s[t] - v;
    if (t == SCAN_T - 1) g_bsum[blockIdx.x] = s[t];
}

__global__ void scan_sums()
{
    __shared__ int s[256];
    int t = threadIdx.x;
    int v = (t < SCAN_NB) ? g_bsum[t] : 0;
    s[t] = v;
    __syncthreads();
    for (int off = 1; off < 256; off <<= 1) {
        int x = (t >= off) ? s[t - off] : 0;
        __syncthreads();
        s[t] += x;
        __syncthreads();
    }
    if (t < SCAN_NB) g_bpre[t] = s[t] - v;
}

__global__ void scan_fixup()
{
    int i = blockIdx.x * blockDim.x + threadIdx.x;
    if (i < NN) g_pos[i] = g_off[i] + g_bpre[i / SCAN_T];
}

// ---------------- scatter ----------------
__global__ void scatter_kernel(const int* __restrict__ ei, const float2* __restrict__ ea)
{
    int e = blockIdx.x * blockDim.x + threadIdx.x;
    if (e >= NE) return;
    int d = load_dst(ei, e);
    int p = atomicAdd(&g_pos[d], 1);
    float2 a = ea[e];
    g_sedge[p] = make_int4(load_src(ei, e), d, __float_as_int(a.x), __float_as_int(a.y));
}

// ---------------- fused edge MLP: consecutive EPT=4, branchless merge network ----------------
__global__ void __launch_bounds__(256) edge_fused_kernel()
{
    __shared__ unsigned sW1h[5*8];     // half2(W1[2j][i], W1[2j+1][i]) at [i*8+jp]
    __shared__ unsigned sb1h[8];
    __shared__ unsigned sW2h[16*16];   // half2(W2[2jp][k], W2[2jp+1][k]) at [k*16+jp]
    __shared__ unsigned sb2h[16];

    for (int i = threadIdx.x; i < 40; i += blockDim.x) {
        int in = i >> 3, jp = i & 7;
        __half2 h = __floats2half2_rn(g_W1[(2*jp)*5 + in], g_W1[(2*jp+1)*5 + in]);
        sW1h[i] = *reinterpret_cast<unsigned*>(&h);
    }
    for (int i = threadIdx.x; i < 8; i += blockDim.x) {
        __half2 h = __floats2half2_rn(g_b1[2*i], g_b1[2*i+1]);
        sb1h[i] = *reinterpret_cast<unsigned*>(&h);
    }
    for (int i = threadIdx.x; i < 256; i += blockDim.x) {
        int k = i >> 4, jp = i & 15;
        __half2 h = __floats2half2_rn(g_W2[(2*jp)*16 + k], g_W2[(2*jp+1)*16 + k]);
        sW2h[i] = *reinterpret_cast<unsigned*>(&h);
    }
    for (int i = threadIdx.x; i < 16; i += blockDim.x) {
        __half2 h = __floats2half2_rn(g_b2[2*i], g_b2[2*i+1]);
        sb2h[i] = *reinterpret_cast<unsigned*>(&h);
    }
    __syncthreads();

    const unsigned FULL = 0xffffffffu;
    int lane = threadIdx.x & 31;
    int base_e = (blockIdx.x * blockDim.x + threadIdx.x) * EPT;  // 4 consecutive sorted edges

    int dst[EPT];
    unsigned m1[EPT][8];

    #pragma unroll
    for (int i = 0; i < EPT; i++) {
        int4 rec = g_sedge[base_e + i];
        dst[i] = rec.y;
        float4 xv = g_xp[rec.x];

        __half2 i0 = __half2half2(__float2half(xv.x));
        __half2 i1 = __half2half2(__float2half(xv.y));
        __half2 i2 = __half2half2(__float2half(xv.z));
        __half2 i3 = __half2half2(__float2half(__int_as_float(rec.z)));
        __half2 i4 = __half2half2(__float2half(__int_as_float(rec.w)));

        #pragma unroll
        for (int jp = 0; jp < 8; jp++) {
            __half2 a = *reinterpret_cast<__half2*>(&sb1h[jp]);
            a = __hfma2(*reinterpret_cast<__half2*>(&sW1h[0*8 + jp]), i0, a);
            a = __hfma2(*reinterpret_cast<__half2*>(&sW1h[1*8 + jp]), i1, a);
            a = __hfma2(*reinterpret_cast<__half2*>(&sW1h[2*8 + jp]), i2, a);
            a = __hfma2(*reinterpret_cast<__half2*>(&sW1h[3*8 + jp]), i3, a);
            a = __hfma2(*reinterpret_cast<__half2*>(&sW1h[4*8 + jp]), i4, a);
            m1[i][jp] = hmax2_bits(*reinterpret_cast<unsigned*>(&a), 0u);
        }
    }

    // ---- key-derived predicates (hoisted across the two phases) ----
    bool same01 = (dst[0] == dst[1]);
    bool same12 = (dst[1] == dst[2]);
    bool same23 = (dst[2] == dst[3]);
    int  k0 = dst[0];

    int kn1  = __shfl_down_sync(FULL, k0, 1);
    int kn2  = __shfl_down_sync(FULL, k0, 2);
    int kn4  = __shfl_down_sync(FULL, k0, 4);
    int kn8  = __shfl_down_sync(FULL, k0, 8);
    int kn16 = __shfl_down_sync(FULL, k0, 16);
    bool take1  = (lane + 1  < 32) && (kn1  == k0);
    bool take2  = (lane + 2  < 32) && (kn2  == k0);
    bool take4  = (lane + 4  < 32) && (kn4  == k0);
    bool take8  = (lane + 8  < 32) && (kn8  == k0);
    bool take16 = (lane + 16 < 32) && (kn16 == k0);

    bool cv  = (lane < 31) && (kn1 == dst[3]);       // next lane's first key continues our tail run
    bool cm0 = cv && (dst[0] == dst[3]);
    bool cm1 = cv && (dst[1] == dst[3]);
    bool cm2 = cv && (dst[2] == dst[3]);

    int upk3 = __shfl_up_sync(FULL, dst[3], 1);
    bool h0 = (lane == 0) || (upk3 != dst[0]);
    bool h1 = !same01;
    bool h2 = !same12;
    bool h3 = !same23;

    // ---- two phases over output halves ----
    #pragma unroll
    for (int ph = 0; ph < 2; ph++) {
        unsigned acc[EPT][8];
        #pragma unroll
        for (int i = 0; i < EPT; i++)
            #pragma unroll
            for (int jp = 0; jp < 8; jp++) acc[i][jp] = sb2h[ph*8 + jp];

        #pragma unroll
        for (int kp = 0; kp < 8; kp++) {
            __half2 lo[EPT], hi[EPT];
            #pragma unroll
            for (int i = 0; i < EPT; i++) {
                __half2 mk = *reinterpret_cast<__half2*>(&m1[i][kp]);
                lo[i] = __low2half2(mk);
                hi[i] = __high2half2(mk);
            }
            #pragma unroll
            for (int jp = 0; jp < 8; jp++) {
                __half2 w0 = *reinterpret_cast<__half2*>(&sW2h[(2*kp)*16   + ph*8 + jp]);
                __half2 w1 = *reinterpret_cast<__half2*>(&sW2h[(2*kp+1)*16 + ph*8 + jp]);
                #pragma unroll
                for (int i = 0; i < EPT; i++) {
                    __half2 a = *reinterpret_cast<__half2*>(&acc[i][jp]);
                    a = __hfma2(w0, lo[i], a);
                    a = __hfma2(w1, hi[i], a);
                    acc[i][jp] = *reinterpret_cast<unsigned*>(&a);
                }
            }
        }
        #pragma unroll
        for (int i = 0; i < EPT; i++)
            #pragma unroll
            for (int jp = 0; jp < 8; jp++) acc[i][jp] = hmax2_bits(acc[i][jp], 0u);

        // local suffix merges (sequential, static indices, predicated)
        #pragma unroll
        for (int q = 0; q < 8; q++) if (same23) acc[2][q] = hmax2_bits(acc[2][q], acc[3][q]);
        #pragma unroll
        for (int q = 0; q < 8; q++) if (same12) acc[1][q] = hmax2_bits(acc[1][q], acc[2][q]);
        #pragma unroll
        for (int q = 0; q < 8; q++) if (same01) acc[0][q] = hmax2_bits(acc[0][q], acc[1][q]);

        // warp segmented suffix on element 0 (keys ascending across lanes)
        #pragma unroll
        for (int q = 0; q < 8; q++) { unsigned o = __shfl_down_sync(FULL, acc[0][q], 1);  if (take1)  acc[0][q] = hmax2_bits(acc[0][q], o); }
        #pragma unroll
        for (int q = 0; q < 8; q++) { unsigned o = __shfl_down_sync(FULL, acc[0][q], 2);  if (take2)  acc[0][q] = hmax2_bits(acc[0][q], o); }
        #pragma unroll
        for (int q = 0; q < 8; q++) { unsigned o = __shfl_down_sync(FULL, acc[0][q], 4);  if (take4)  acc[0][q] = hmax2_bits(acc[0][q], o); }
        #pragma unroll
        for (int q = 0; q < 8; q++) { unsigned o = __shfl_down_sync(FULL, acc[0][q], 8);  if (take8)  acc[0][q] = hmax2_bits(acc[0][q], o); }
        #pragma unroll
        for (int q = 0; q < 8; q++) { unsigned o = __shfl_down_sync(FULL, acc[0][q], 16); if (take16) acc[0][q] = hmax2_bits(acc[0][q], o); }

        // carry from lane+1's full-segment element 0 into our tail run
        #pragma unroll
        for (int q = 0; q < 8; q++) {
            unsigned cq = __shfl_down_sync(FULL, acc[0][q], 1);
            if (cv)  acc[3][q] = hmax2_bits(acc[3][q], cq);
            if (cm2) acc[2][q] = hmax2_bits(acc[2][q], cq);
            if (cm1) acc[1][q] = hmax2_bits(acc[1][q], cq);
            if (cm0) acc[0][q] = hmax2_bits(acc[0][q], cq);
        }

        // flush heads (reads only; piecewise atomics are exact)
        #pragma unroll
        for (int i = 0; i < EPT; i++) {
            bool head = (i == 0) ? h0 : (i == 1) ? h1 : (i == 2) ? h2 : h3;
            if (head) {
                unsigned* basep = &g_agg[(unsigned)dst[i] * 32u + ph * 16];
                #pragma unroll
                for (int q = 0; q < 8; q++) {
                    float2 f = __half22float2(*reinterpret_cast<__half2*>(&acc[i][q]));
                    unsigned b0 = __float_as_uint(f.x);
                    unsigned b1 = __float_as_uint(f.y);
                    if (b0) atomicMax(&basep[2*q],     b0);
                    if (b1) atomicMax(&basep[2*q + 1], b1);
                }
            }
        }
    }
}

// ---------------- node MLP (re-zeros agg in-place for next iteration) ----------------
__global__ void __launch_bounds__(256) node_kernel(float* __restrict__ out, int last)
{
    __shared__ float sW3[16*35], sb3[16], sW4[16], sb4[1];
    for (int i = threadIdx.x; i < 16*35; i += blockDim.x) sW3[i] = g_W3[i];
    for (int i = threadIdx.x; i < 16;    i += blockDim.x) sb3[i] = g_b3[i];
    for (int i = threadIdx.x; i < 16;    i += blockDim.x) sW4[i] = g_W4[i];
    if (threadIdx.x == 0) sb4[0] = g_b4[0];
    __syncthreads();

    int i = blockIdx.x * blockDim.x + threadIdx.x;
    if (i >= NN) return;

    float4 xv = g_xp[i];
    float h[35];
    h[0] = xv.x; h[1] = xv.y; h[2] = xv.z;

    uint4* ar = reinterpret_cast<uint4*>(&g_agg[(size_t)i * 32]);
    #pragma unroll
    for (int q = 0; q < 8; q++) {
        uint4 v = ar[q];
        h[3 + 4*q + 0] = __uint_as_float(v.x);
        h[3 + 4*q + 1] = __uint_as_float(v.y);
        h[3 + 4*q + 2] = __uint_as_float(v.z);
        h[3 + 4*q + 3] = __uint_as_float(v.w);
    }
    // re-zero agg while lines are hot
    #pragma unroll
    for (int q = 0; q < 8; q++) ar[q] = make_uint4(0u, 0u, 0u, 0u);

    float t[16];
    #pragma unroll
    for (int j = 0; j < 16; j++) {
        float s = sb3[j];
        #pragma unroll
        for (int k = 0; k < 35; k++) s = fmaf(sW3[j*35 + k], h[k], s);
        t[j] = fmaxf(s, 0.f);
    }

    float z = sb4[0];
    #pragma unroll
    for (int k = 0; k < 16; k++) z = fmaf(sW4[k], t[k], z);

    float comb = 1.f / (1.f + expf(-z));
    reinterpret_cast<float*>(&g_xp[i])[2] = comb;

    if (last) {
        out[3*i + 0] = xv.x;
        out[3*i + 1] = xv.y;
        out[3*i + 2] = comb;
    }
}

// ---------------- launch ----------------
extern "C" void kernel_launch(void* const* d_in, const int* in_sizes, int n_in,
                              void* d_out, int out_size)
{
    const float* x  = (const float*)d_in[0];
    const float* ea = (const float*)d_in[1];
    const void*  ei = d_in[2];
    const float* P[24];
    for (int i = 0; i < 24; i++) P[i] = (const float*)d_in[3 + i];

    prep_init<<<((NN * 32) / 4 + 255) / 256, 256>>>(x);   // flag reset + zero cnt/agg + pack x
    detect_layout<<<2, 256>>>((const unsigned*)ei);

    prep_weights<<<4, 256>>>(
        P[0],  P[1],  P[2],  P[3],  P[4],  P[5],
        P[6],  P[7],  P[8],  P[9],  P[10], P[11],
        P[12], P[13], P[14], P[15], P[16], P[17],
        P[18], P[19], P[20], P[21], P[22], P[23]);

    hist_kernel<<<(NE + 255) / 256, 256>>>((const int*)ei);
    scan_blocks<<<SCAN_NB, SCAN_T>>>();
    scan_sums<<<1, 256>>>();
    scan_fixup<<<(NN + 255) / 256, 256>>>();
    scatter_kernel<<<(NE + 255) / 256, 256>>>((const int*)ei, (const float2*)ea);

    const int edge_blocks = NE / (256 * EPT);       // 3125
    const int node_blocks = (NN + 255) / 256;       // 391

    for (int it = 0; it < 3; it++) {
        edge_fused_kernel<<<edge_blocks, 256>>>();
        node_kernel<<<node_blocks, 256>>>((float*)d_out, it == 2 ? 1 : 0);
    }
}

// round 11
// speedup vs baseline: 1.4236x; 1.4236x over previous
#include <cuda_runtime.h>
#include <cuda_fp16.h>
#include <math.h>

#define NE 3200000
#define NN 100000
#define EPT 4
#define SCAN_T 512
#define SCAN_NB 196   // 196*512 = 100352 >= NN

// ---------------- device state ----------------
__device__ float g_W1[16*5];
__device__ float g_b1[16];
__device__ float g_W2[32*16];
__device__ float g_b2[32];
__device__ float g_W3[16*35];
__device__ float g_b3[16];
__device__ float g_W4[16];
__device__ float g_b4[1];

__device__ int4   g_sedge[NE];      // dst-sorted {src, dst, ea.x bits, ea.y bits}
__device__ int    g_cnt[NN];
__device__ int    g_off[NN];
__device__ int    g_pos[NN];
__device__ int    g_bsum[SCAN_NB];
__device__ int    g_bpre[SCAN_NB];

__device__ float4   g_xp[NN];       // (x0, x1, x2, unused)
__device__ unsigned g_agg[NN * 32]; // fp32 bit patterns, all values >= 0
__device__ int      g_is_i32;       // zero-init at load; monotonic (never reset; input-determined)

__device__ __forceinline__ float softplusf(float v) {
    return (v > 20.f) ? v : log1pf(expf(v));
}

__device__ __forceinline__ unsigned hmax2_bits(unsigned a, unsigned b) {
    __half2 ha = *reinterpret_cast<__half2*>(&a);
    __half2 hb = *reinterpret_cast<__half2*>(&b);
    __half2 r = __hmax2(ha, hb);
    return *reinterpret_cast<unsigned*>(&r);
}

// ---------------- fused prep: detect layout, zero cnt+agg, pack x ----------------
__global__ void prep_init(const float* __restrict__ x, const unsigned* __restrict__ ei_words)
{
    int i = blockIdx.x * blockDim.x + threadIdx.x;
    if (i < 512) {
        // int64 layout -> odd words are high words of values < NN -> all zero.
        if (ei_words[2*i + 1] != 0u) atomicExch(&g_is_i32, 1);
    }
    if (i < NN) {
        g_cnt[i] = 0;
        g_xp[i] = make_float4(x[3*i + 0], x[3*i + 1], x[3*i + 2], 0.f);
    }
    if (i < (NN * 32) / 4)
        reinterpret_cast<uint4*>(g_agg)[i] = make_uint4(0u, 0u, 0u, 0u);
}

// ---------------- prep: sample Bayesian weights ----------------
__global__ void prep_weights(
    const float* w1m, const float* w1r, const float* b1m, const float* b1r, const float* e1w, const float* e1b,
    const float* w2m, const float* w2r, const float* b2m, const float* b2r, const float* e2w, const float* e2b,
    const float* w3m, const float* w3r, const float* b3m, const float* b3r, const float* e3w, const float* e3b,
    const float* w4m, const float* w4r, const float* b4m, const float* b4r, const float* e4w, const float* e4b)
{
    int t = blockIdx.x * blockDim.x + threadIdx.x;
    int stride = gridDim.x * blockDim.x;
    for (int i = t; i < 16*5;  i += stride) g_W1[i] = w1m[i] + softplusf(w1r[i]) * e1w[i];
    for (int i = t; i < 16;    i += stride) g_b1[i] = b1m[i] + softplusf(b1r[i]) * e1b[i];
    for (int i = t; i < 32*16; i += stride) g_W2[i] = w2m[i] + softplusf(w2r[i]) * e2w[i];
    for (int i = t; i < 32;    i += stride) g_b2[i] = b2m[i] + softplusf(b2r[i]) * e2b[i];
    for (int i = t; i < 16*35; i += stride) g_W3[i] = w3m[i] + softplusf(w3r[i]) * e3w[i];
    for (int i = t; i < 16;    i += stride) g_b3[i] = b3m[i] + softplusf(b3r[i]) * e3b[i];
    for (int i = t; i < 16;    i += stride) g_W4[i] = w4m[i] + softplusf(w4r[i]) * e4w[i];
    for (int i = t; i < 1;     i += stride) g_b4[i] = b4m[i] + softplusf(b4r[i]) * e4b[i];
}

// ---------------- helpers to read edge index in either width ----------------
__device__ __forceinline__ int load_src(const int* ei, int e) {
    int s = g_is_i32 ? ei[e] : ei[2*e];
    return ((unsigned)s >= NN) ? 0 : s;
}
__device__ __forceinline__ int load_dst(const int* ei, int e) {
    int d = g_is_i32 ? ei[NE + e] : ei[2*(NE + e)];
    return ((unsigned)d >= NN) ? 0 : d;
}

// ---------------- histogram: 4 edges/thread for MLP ----------------
__global__ void hist_kernel(const int* __restrict__ ei)
{
    int base = blockIdx.x * blockDim.x * 4 + threadIdx.x;
    int d0 = load_dst(ei, base + 0*256);
    int d1 = load_dst(ei, base + 1*256);
    int d2 = load_dst(ei, base + 2*256);
    int d3 = load_dst(ei, base + 3*256);
    atomicAdd(&g_cnt[d0], 1);
    atomicAdd(&g_cnt[d1], 1);
    atomicAdd(&g_cnt[d2], 1);
    atomicAdd(&g_cnt[d3], 1);
}

// ---------------- scan ----------------
__global__ void scan_blocks()
{
    __shared__ int s[SCAN_T];
    int t = threadIdx.x;
    int i = blockIdx.x * SCAN_T + t;
    int v = (i < NN) ? g_cnt[i] : 0;
    s[t] = v;
    __syncthreads();
    for (int off = 1; off < SCAN_T; off <<= 1) {
        int x = (t >= off) ? s[t - off] : 0;
        __syncthreads();
        s[t] += x;
        __syncthreads();
    }
    if (i < NN) g_off[i] = s[t] - v;
    if (t == SCAN_T - 1) g_bsum[blockIdx.x] = s[t];
}

__global__ void scan_sums()
{
    __shared__ int s[256];
    int t = threadIdx.x;
    int v = (t < SCAN_NB) ? g_bsum[t] : 0;
    s[t] = v;
    __syncthreads();
    for (int off = 1; off < 256; off <<= 1) {
        int x = (t >= off) ? s[t - off] : 0;
        __syncthreads();
        s[t] += x;
        __syncthreads();
    }
    if (t < SCAN_NB) g_bpre[t] = s[t] - v;
}

__global__ void scan_fixup()
{
    int i = blockIdx.x * blockDim.x + threadIdx.x;
    if (i < NN) g_pos[i] = g_off[i] + g_bpre[i / SCAN_T];
}

// ---------------- scatter: 2 edges/thread for MLP ----------------
__global__ void scatter_kernel(const int* __restrict__ ei, const float2* __restrict__ ea)
{
    int base = blockIdx.x * blockDim.x * 2 + threadIdx.x;
    int e0 = base, e1 = base + 256;
    int d0 = load_dst(ei, e0);
    int d1 = load_dst(ei, e1);
    int s0 = load_src(ei, e0);
    int s1 = load_src(ei, e1);
    float2 a0 = ea[e0];
    float2 a1 = ea[e1];
    int p0 = atomicAdd(&g_pos[d0], 1);
    int p1 = atomicAdd(&g_pos[d1], 1);
    g_sedge[p0] = make_int4(s0, d0, __float_as_int(a0.x), __float_as_int(a0.y));
    g_sedge[p1] = make_int4(s1, d1, __float_as_int(a1.x), __float_as_int(a1.y));
}

// ---------------- fused edge MLP (fp16, strided EPT=4, two output phases) ----------------
__global__ void __launch_bounds__(256) edge_fused_kernel()
{
    __shared__ unsigned sW1h[5*8];     // half2(W1[2j][i], W1[2j+1][i]) at [i*8+jp]
    __shared__ unsigned sb1h[8];
    __shared__ unsigned sW2h[16*16];   // half2(W2[2jp][k], W2[2jp+1][k]) at [k*16+jp]
    __shared__ unsigned sb2h[16];

    for (int i = threadIdx.x; i < 40; i += blockDim.x) {
        int in = i >> 3, jp = i & 7;
        __half2 h = __floats2half2_rn(g_W1[(2*jp)*5 + in], g_W1[(2*jp+1)*5 + in]);
        sW1h[i] = *reinterpret_cast<unsigned*>(&h);
    }
    for (int i = threadIdx.x; i < 8; i += blockDim.x) {
        __half2 h = __floats2half2_rn(g_b1[2*i], g_b1[2*i+1]);
        sb1h[i] = *reinterpret_cast<unsigned*>(&h);
    }
    for (int i = threadIdx.x; i < 256; i += blockDim.x) {
        int k = i >> 4, jp = i & 15;
        __half2 h = __floats2half2_rn(g_W2[(2*jp)*16 + k], g_W2[(2*jp+1)*16 + k]);
        sW2h[i] = *reinterpret_cast<unsigned*>(&h);
    }
    for (int i = threadIdx.x; i < 16; i += blockDim.x) {
        __half2 h = __floats2half2_rn(g_b2[2*i], g_b2[2*i+1]);
        sb2h[i] = *reinterpret_cast<unsigned*>(&h);
    }
    __syncthreads();

    const unsigned FULL = 0xffffffffu;
    int lane = threadIdx.x & 31;
    int block_base = blockIdx.x * blockDim.x * EPT;

    // load 4 strided edges (warp holds 32 consecutive sorted edges per window)
    int dst[EPT];
    unsigned m1[EPT][8];

    #pragma unroll
    for (int i = 0; i < EPT; i++) {
        int4 rec = g_sedge[block_base + i * 256 + threadIdx.x];
        dst[i] = rec.y;
        float4 xv = g_xp[rec.x];

        __half2 i0 = __half2half2(__float2half(xv.x));
        __half2 i1 = __half2half2(__float2half(xv.y));
        __half2 i2 = __half2half2(__float2half(xv.z));
        __half2 i3 = __half2half2(__float2half(__int_as_float(rec.z)));
        __half2 i4 = __half2half2(__float2half(__int_as_float(rec.w)));

        #pragma unroll
        for (int jp = 0; jp < 8; jp++) {
            __half2 a = *reinterpret_cast<__half2*>(&sb1h[jp]);
            a = __hfma2(*reinterpret_cast<__half2*>(&sW1h[0*8 + jp]), i0, a);
            a = __hfma2(*reinterpret_cast<__half2*>(&sW1h[1*8 + jp]), i1, a);
            a = __hfma2(*reinterpret_cast<__half2*>(&sW1h[2*8 + jp]), i2, a);
            a = __hfma2(*reinterpret_cast<__half2*>(&sW1h[3*8 + jp]), i3, a);
            a = __hfma2(*reinterpret_cast<__half2*>(&sW1h[4*8 + jp]), i4, a);
            m1[i][jp] = hmax2_bits(*reinterpret_cast<unsigned*>(&a), 0u);
        }
    }

    // hoisted per-window key predicates (shared by both phases)
    bool t1[EPT], t2[EPT], t4[EPT], t8[EPT], t16[EPT], hd[EPT];
    #pragma unroll
    for (int i = 0; i < EPT; i++) {
        int key = dst[i];
        int kn1  = __shfl_down_sync(FULL, key, 1);
        int kn2  = __shfl_down_sync(FULL, key, 2);
        int kn4  = __shfl_down_sync(FULL, key, 4);
        int kn8  = __shfl_down_sync(FULL, key, 8);
        int kn16 = __shfl_down_sync(FULL, key, 16);
        t1[i]  = (lane + 1  < 32) && (kn1  == key);
        t2[i]  = (lane + 2  < 32) && (kn2  == key);
        t4[i]  = (lane + 4  < 32) && (kn4  == key);
        t8[i]  = (lane + 8  < 32) && (kn8  == key);
        t16[i] = (lane + 16 < 32) && (kn16 == key);
        int prev = __shfl_up_sync(FULL, key, 1);
        hd[i] = (lane == 0) || (prev != key);
    }

    // two phases over output halves: jp 0..7 (agg cols 0..15), jp 8..15 (cols 16..31)
    #pragma unroll
    for (int ph = 0; ph < 2; ph++) {
        unsigned acc[EPT][8];
        #pragma unroll
        for (int i = 0; i < EPT; i++)
            #pragma unroll
            for (int jp = 0; jp < 8; jp++) acc[i][jp] = sb2h[ph*8 + jp];

        #pragma unroll
        for (int kp = 0; kp < 8; kp++) {
            __half2 lo[EPT], hi[EPT];
            #pragma unroll
            for (int i = 0; i < EPT; i++) {
                __half2 mk = *reinterpret_cast<__half2*>(&m1[i][kp]);
                lo[i] = __low2half2(mk);
                hi[i] = __high2half2(mk);
            }
            #pragma unroll
            for (int jp = 0; jp < 8; jp++) {
                __half2 w0 = *reinterpret_cast<__half2*>(&sW2h[(2*kp)*16   + ph*8 + jp]);
                __half2 w1 = *reinterpret_cast<__half2*>(&sW2h[(2*kp+1)*16 + ph*8 + jp]);
                #pragma unroll
                for (int i = 0; i < EPT; i++) {
                    __half2 a = *reinterpret_cast<__half2*>(&acc[i][jp]);
                    a = __hfma2(w0, lo[i], a);
                    a = __hfma2(w1, hi[i], a);
                    acc[i][jp] = *reinterpret_cast<unsigned*>(&a);
                }
            }
        }
        #pragma unroll
        for (int i = 0; i < EPT; i++)
            #pragma unroll
            for (int jp = 0; jp < 8; jp++) acc[i][jp] = hmax2_bits(acc[i][jp], 0u);

        // per-window segmented suffix max + head flush
        #pragma unroll
        for (int i = 0; i < EPT; i++) {
            #pragma unroll
            for (int q = 0; q < 8; q++) { unsigned o = __shfl_down_sync(FULL, acc[i][q], 1);  if (t1[i])  acc[i][q] = hmax2_bits(acc[i][q], o); }
            #pragma unroll
            for (int q = 0; q < 8; q++) { unsigned o = __shfl_down_sync(FULL, acc[i][q], 2);  if (t2[i])  acc[i][q] = hmax2_bits(acc[i][q], o); }
            #pragma unroll
            for (int q = 0; q < 8; q++) { unsigned o = __shfl_down_sync(FULL, acc[i][q], 4);  if (t4[i])  acc[i][q] = hmax2_bits(acc[i][q], o); }
            #pragma unroll
            for (int q = 0; q < 8; q++) { unsigned o = __shfl_down_sync(FULL, acc[i][q], 8);  if (t8[i])  acc[i][q] = hmax2_bits(acc[i][q], o); }
            #pragma unroll
            for (int q = 0; q < 8; q++) { unsigned o = __shfl_down_sync(FULL, acc[i][q], 16); if (t16[i]) acc[i][q] = hmax2_bits(acc[i][q], o); }

            if (hd[i]) {
                unsigned* basep = &g_agg[(unsigned)dst[i] * 32u + ph * 16];
                #pragma unroll
                for (int q = 0; q < 8; q++) {
                    float2 f = __half22float2(*reinterpret_cast<__half2*>(&acc[i][q]));
                    unsigned b0 = __float_as_uint(f.x);
                    unsigned b1 = __float_as_uint(f.y);
                    if (b0) atomicMax(&basep[2*q],     b0);
                    if (b1) atomicMax(&basep[2*q + 1], b1);
                }
            }
        }
    }
}

// ---------------- node MLP (re-zeros agg in-place for next iteration) ----------------
__global__ void __launch_bounds__(256) node_kernel(float* __restrict__ out, int last)
{
    __shared__ float sW3[16*35], sb3[16], sW4[16], sb4[1];
    for (int i = threadIdx.x; i < 16*35; i += blockDim.x) sW3[i] = g_W3[i];
    for (int i = threadIdx.x; i < 16;    i += blockDim.x) sb3[i] = g_b3[i];
    for (int i = threadIdx.x; i < 16;    i += blockDim.x) sW4[i] = g_W4[i];
    if (threadIdx.x == 0) sb4[0] = g_b4[0];
    __syncthreads();

    int i = blockIdx.x * blockDim.x + threadIdx.x;
    if (i >= NN) return;

    float4 xv = g_xp[i];
    float h[35];
    h[0] = xv.x; h[1] = xv.y; h[2] = xv.z;

    uint4* ar = reinterpret_cast<uint4*>(&g_agg[(size_t)i * 32]);
    #pragma unroll
    for (int q = 0; q < 8; q++) {
        uint4 v = ar[q];
        h[3 + 4*q + 0] = __uint_as_float(v.x);
        h[3 + 4*q + 1] = __uint_as_float(v.y);
        h[3 + 4*q + 2] = __uint_as_float(v.z);
        h[3 + 4*q + 3] = __uint_as_float(v.w);
    }
    // re-zero agg while lines are hot
    #pragma unroll
    for (int q = 0; q < 8; q++) ar[q] = make_uint4(0u, 0u, 0u, 0u);

    float t[16];
    #pragma unroll
    for (int j = 0; j < 16; j++) {
        float s = sb3[j];
        #pragma unroll
        for (int k = 0; k < 35; k++) s = fmaf(sW3[j*35 + k], h[k], s);
        t[j] = fmaxf(s, 0.f);
    }

    float z = sb4[0];
    #pragma unroll
    for (int k = 0; k < 16; k++) z = fmaf(sW4[k], t[k], z);

    float comb = 1.f / (1.f + expf(-z));
    reinterpret_cast<float*>(&g_xp[i])[2] = comb;

    if (last) {
        out[3*i + 0] = xv.x;
        out[3*i + 1] = xv.y;
        out[3*i + 2] = comb;
    }
}

// ---------------- launch ----------------
extern "C" void kernel_launch(void* const* d_in, const int* in_sizes, int n_in,
                              void* d_out, int out_size)
{
    const float* x  = (const float*)d_in[0];
    const float* ea = (const float*)d_in[1];
    const void*  ei = d_in[2];
    const float* P[24];
    for (int i = 0; i < 24; i++) P[i] = (const float*)d_in[3 + i];

    prep_init<<<((NN * 32) / 4 + 255) / 256, 256>>>(x, (const unsigned*)ei);

    prep_weights<<<4, 256>>>(
        P[0],  P[1],  P[2],  P[3],  P[4],  P[5],
        P[6],  P[7],  P[8],  P[9],  P[10], P[11],
        P[12], P[13], P[14], P[15], P[16], P[17],
        P[18], P[19], P[20], P[21], P[22], P[23]);

    hist_kernel<<<NE / (256 * 4), 256>>>((const int*)ei);        // 3125 blocks
    scan_blocks<<<SCAN_NB, SCAN_T>>>();
    scan_sums<<<1, 256>>>();
    scan_fixup<<<(NN + 255) / 256, 256>>>();
    scatter_kernel<<<NE / (256 * 2), 256>>>((const int*)ei, (const float2*)ea);  // 6250 blocks

    const int edge_blocks = NE / (256 * EPT);       // 3125
    const int node_blocks = (NN + 255) / 256;       // 391

    for (int it = 0; it < 3; it++) {
        edge_fused_kernel<<<edge_blocks, 256>>>();
        node_kernel<<<node_blocks, 256>>>((float*)d_out, it == 2 ? 1 : 0);
    }
}